// round 1
// baseline (speedup 1.0000x reference)
#include <cuda_runtime.h>

// PointPillarsBEV: PFN (10->64 linear + relu + max over 32 pts) then scatter-add
// into a (B, C, 512, 512) BEV canvas.
//
// K1: zero the 268MB output (memory-bound, ~40us)
// K2: one warp per pillar; packed f32x2 FMA PFN + fp32 atomicAdd scatter
//     (fma-pipe bound, ~28us)

#define NPTS 32
#define DIMS 10
#define CH 64
#define BEV_H 512
#define BEV_W 512
#define HWSZ (BEV_H * BEV_W)
#define P_PER_B 12000
#define BATCH 4
#define PILLARS_TOTAL (BATCH * P_PER_B)
#define WPB 8          // warps per block
#define SHS 36         // padded shared row stride (floats): banks (4d+n)%32, 16B aligned rows

typedef unsigned long long ull;

__device__ __forceinline__ ull pk2(float a, float b) {
    ull r;
    asm("mov.b64 %0, {%1, %2};" : "=l"(r) : "f"(a), "f"(b));
    return r;
}

__device__ __forceinline__ void fma2(ull& acc, ull x, ull w) {
    // packed fp32x2 FMA: 2 FMAs per instruction (only reachable via PTX)
    asm("fma.rn.f32x2 %0, %1, %2, %0;" : "+l"(acc) : "l"(x), "l"(w));
}

__device__ __forceinline__ float2 up2(ull v) {
    float2 r;
    asm("mov.b64 {%0, %1}, %2;" : "=f"(r.x), "=f"(r.y) : "l"(v));
    return r;
}

__global__ void __launch_bounds__(256) zero_out_kernel(float4* __restrict__ out) {
    unsigned i = blockIdx.x * blockDim.x + threadIdx.x;
    out[i] = make_float4(0.f, 0.f, 0.f, 0.f);
}

__global__ void __launch_bounds__(256) pfn_scatter_kernel(
    const float* __restrict__ pillars,   // (B, P, NPTS, DIMS)
    const int*   __restrict__ coords,    // (B, P, 2)  [y, x]
    const float* __restrict__ w,         // (DIMS, CH)
    const float* __restrict__ bias,      // (CH)
    float*       __restrict__ out)       // (B, CH, H, W)
{
    __shared__ __align__(16) float sh[WPB][DIMS * SHS];
    const int warp = threadIdx.x >> 5;
    const int lane = threadIdx.x & 31;
    const int pillar = blockIdx.x * WPB + warp;
    if (pillar >= PILLARS_TOTAL) return;

    // Duplicated weight pairs (w,w) for the two channels this lane owns:
    // c0 = lane, c1 = lane + 32 (coalesced weight loads).
    ull w0[DIMS], w1[DIMS];
#pragma unroll
    for (int d = 0; d < DIMS; d++) {
        float a = w[d * CH + lane];
        float c = w[d * CH + 32 + lane];
        w0[d] = pk2(a, a);
        w1[d] = pk2(c, c);
    }
    const float b0 = bias[lane];
    const float b1 = bias[lane + 32];
    const ull bd0 = pk2(b0, b0);
    const ull bd1 = pk2(b1, b1);

    // Stage pillar points transposed: sh[d][n]. Coalesced global read of
    // 320 contiguous floats, scattered (lightly-conflicted) shared write.
    const float* src = pillars + (size_t)pillar * (NPTS * DIMS);
#pragma unroll
    for (int k = 0; k < DIMS; k++) {
        int j = k * 32 + lane;
        float v = src[j];
        int n = j / DIMS;
        int dd = j - n * DIMS;
        sh[warp][dd * SHS + n] = v;
    }
    __syncwarp();

    // max over points of relu(v) == max(0, max over points of v)
    float m0 = 0.f, m1 = 0.f;
#pragma unroll
    for (int n0 = 0; n0 < NPTS; n0 += 4) {
        ull a00 = bd0, a01 = bd0, a10 = bd1, a11 = bd1;
#pragma unroll
        for (int d = 0; d < DIMS; d++) {
            // 16B broadcast load: two pre-packed point-pairs for dim d
            ulonglong2 xv = *reinterpret_cast<const ulonglong2*>(&sh[warp][d * SHS + n0]);
            fma2(a00, xv.x, w0[d]);
            fma2(a01, xv.y, w0[d]);
            fma2(a10, xv.x, w1[d]);
            fma2(a11, xv.y, w1[d]);
        }
        float2 v0 = up2(a00), v1 = up2(a01), v2 = up2(a10), v3 = up2(a11);
        m0 = fmaxf(m0, fmaxf(fmaxf(v0.x, v0.y), fmaxf(v1.x, v1.y)));
        m1 = fmaxf(m1, fmaxf(fmaxf(v2.x, v2.y), fmaxf(v3.x, v3.y)));
    }

    const int b = pillar / P_PER_B;
    const int y = coords[2 * pillar];
    const int x = coords[2 * pillar + 1];
    float* o = out + (size_t)b * CH * HWSZ + y * BEV_W + x;
    atomicAdd(o + lane * HWSZ, m0);
    atomicAdd(o + (lane + 32) * HWSZ, m1);
}

extern "C" void kernel_launch(void* const* d_in, const int* in_sizes, int n_in,
                              void* d_out, int out_size) {
    const float* pillars = (const float*)d_in[0];
    const int*   coords  = (const int*)d_in[1];
    const float* w       = (const float*)d_in[2];
    const float* bias    = (const float*)d_in[3];
    float* out = (float*)d_out;

    // out_size = 4*64*512*512 = 67,108,864 floats = 16,777,216 float4
    int n4 = out_size / 4;
    zero_out_kernel<<<n4 / 256, 256>>>((float4*)out);

    pfn_scatter_kernel<<<PILLARS_TOTAL / WPB, 256>>>(pillars, coords, w, bias, out);
}